// round 13
// baseline (speedup 1.0000x reference)
#include <cuda_runtime.h>
#include <cuda_fp16.h>
#include <math.h>
#include <stdint.h>

// loss = -mean_j [ alpha*e2_j + logsumexp_i( alpha*z2_i - 2*alpha*<z_i,e_j> ) ]
//        + 0.5*D*(2*ls - 1) + log(N)
// fp16 mma.sync.m16n8k16 (fp32 accum) + ldmatrix + XOR-swizzled smem +
// cp.async pipeline. Persistent 148-CTA grid, static schedule (2048 tiles of
// 128j x 256i x 512k). Fragment double buffering. Bulk epilogue exp2 via
// integer Schraudolph (FFMA+CVT+IMNMX on fma/alu pipes) instead of MUFU.

#define NROWS 8192
#define MROWS 8192
#define DDIM  512

#define JTILE 128
#define ITILE 256
#define KT    64                       // k per stage (128B fp16 rows)
#define KSTAGES (DDIM / KT)            // 8
#define SLABS (MROWS / JTILE)          // 64
#define CHUNKS (NROWS / ITILE)         // 32
#define NITEMS (SLABS * CHUNKS)        // 2048
#define GRID 148

#define A_BYTES (JTILE * 128)          // 16384
#define B_BYTES (ITILE * 128)          // 32768
#define STAGE_BYTES (A_BYTES + B_BYTES)
#define NBUF 4

#define LOG2E 1.4426950408889634f
#define LN2   0.6931471805599453f

// Schraudolph exp2: C = 127*2^23 - round(0.043*2^23) (minimax-centered)
#define SEXP2_C 1064992439.0f

#define FIN_BLOCKS (MROWS / 256)       // 32

__device__ __half g_zh[NROWS * DDIM];
__device__ __half g_eh[MROWS * DDIM];
__device__ float g_z2[NROWS];
__device__ float g_e2[MROWS];
__device__ float g_pm[CHUNKS * MROWS];   // per-(chunk,j) max (log2 units)
__device__ float g_ps[CHUNKS * MROWS];   // per-(chunk,j) sum
__device__ double g_acc;
__device__ unsigned int g_cnt;

__device__ __forceinline__ float fast_exp2(float x) {
    float r; asm("ex2.approx.ftz.f32 %0, %1;" : "=f"(r) : "f"(x)); return r;
}
// approx exp2(t - m) where cm = SEXP2_C - 8388608*m; exact 0 on deep underflow
__device__ __forceinline__ float sexp2(float t, float cm) {
    int i = __float2int_rn(fmaf(t, 8388608.f, cm));
    i = max(i, 0);
    return __int_as_float(i);
}
__device__ __forceinline__ void mma_f16(float* d, const uint32_t* a, const uint32_t* b) {
    asm volatile(
        "mma.sync.aligned.m16n8k16.row.col.f32.f16.f16.f32 "
        "{%0,%1,%2,%3}, {%4,%5,%6,%7}, {%8,%9}, {%0,%1,%2,%3};"
        : "+f"(d[0]), "+f"(d[1]), "+f"(d[2]), "+f"(d[3])
        : "r"(a[0]), "r"(a[1]), "r"(a[2]), "r"(a[3]), "r"(b[0]), "r"(b[1]));
}
__device__ __forceinline__ void ldsm_x4(uint32_t& r0, uint32_t& r1,
                                        uint32_t& r2, uint32_t& r3, uint32_t addr) {
    asm volatile("ldmatrix.sync.aligned.m8n8.x4.shared.b16 {%0,%1,%2,%3}, [%4];"
                 : "=r"(r0), "=r"(r1), "=r"(r2), "=r"(r3) : "r"(addr));
}
__device__ __forceinline__ void cp16(void* smem_dst, const void* gmem_src) {
    uint32_t d = (uint32_t)__cvta_generic_to_shared(smem_dst);
    asm volatile("cp.async.cg.shared.global [%0], [%1], 16;"
                 :: "r"(d), "l"(gmem_src) : "memory");
}

// ---- prep: exact fp32 row norms + fp16(rne) copies; zero accumulators ----
__global__ void prep_kernel(const float* __restrict__ Z, const float* __restrict__ E) {
    if (blockIdx.x == 0 && threadIdx.x == 0) { g_acc = 0.0; g_cnt = 0u; }
    int gw = (blockIdx.x * blockDim.x + threadIdx.x) >> 5;
    int lane = threadIdx.x & 31;
    if (gw >= NROWS + MROWS) return;
    const float4* src; uint2* dst;
    if (gw < NROWS) { src = (const float4*)(Z + (size_t)gw * DDIM);
                      dst = (uint2*)(g_zh + (size_t)gw * DDIM); }
    else            { src = (const float4*)(E + (size_t)(gw - NROWS) * DDIM);
                      dst = (uint2*)(g_eh + (size_t)(gw - NROWS) * DDIM); }
    float s = 0.f;
    #pragma unroll
    for (int u = 0; u < DDIM / 4 / 32; u++) {
        float4 v = src[u * 32 + lane];
        s = fmaf(v.x, v.x, s); s = fmaf(v.y, v.y, s);
        s = fmaf(v.z, v.z, s); s = fmaf(v.w, v.w, s);
        __half2 h01 = __floats2half2_rn(v.x, v.y);
        __half2 h23 = __floats2half2_rn(v.z, v.w);
        uint2 w;
        w.x = *reinterpret_cast<uint32_t*>(&h01);
        w.y = *reinterpret_cast<uint32_t*>(&h23);
        dst[u * 32 + lane] = w;
    }
    #pragma unroll
    for (int o = 16; o; o >>= 1) s += __shfl_xor_sync(0xffffffffu, s, o);
    if (lane == 0) { if (gw < NROWS) g_z2[gw] = s; else g_e2[gw - NROWS] = s; }
}

// ---- persistent fused fp16 mma GEMM + per-tile LSE partials ----
__global__ void __launch_bounds__(256, 1) fused_mma_lse(const float* __restrict__ log_sigma) {
    extern __shared__ char smem[];
    char* stg = smem;                                        // NBUF * STAGE_BYTES
    float* az2 = (float*)(smem + NBUF * STAGE_BYTES);        // 2 * ITILE
    float* smm = az2 + 2 * ITILE;                            // 4 * JTILE
    float* sms = smm + 4 * JTILE;                            // 4 * JTILE
    const uint32_t sb32 = (uint32_t)__cvta_generic_to_shared(smem);

    const int tid = threadIdx.x, lane = tid & 31, wid = tid >> 5;
    const int wm = wid & 1, wn = wid >> 1;                   // 2 x 4 warp grid
    const int g = lane >> 2, cql = lane & 3;
    const int cta = blockIdx.x;

    const int nitems = (NITEMS - cta + GRID - 1) / GRID;     // 13 or 14
    const int tot = nitems * KSTAGES;

    // ldmatrix per-lane addressing
    const int rA = ((lane >> 3) & 1) * 8 + (lane & 7);
    const int cA = (lane >> 4) & 1;
    const int rB = ((lane >> 4) & 1) * 8 + (lane & 7);
    const int cB = (lane >> 3) & 1;

    const float ls = __ldg(log_sigma);
    const float alpha = -0.5f * __expf(-2.f * ls);
    const float coefD = LOG2E * (-2.f * alpha);
    const float coefA = LOG2E * alpha;

    float acc[4][8][4];
    #pragma unroll
    for (int mt = 0; mt < 4; mt++)
        #pragma unroll
        for (int nt = 0; nt < 8; nt++)
            #pragma unroll
            for (int q = 0; q < 4; q++) acc[mt][nt][q] = 0.f;

    auto issue_stage = [&](int ss) {
        int q = ss >> 3, ks = ss & (KSTAGES - 1);
        int item = cta + q * GRID;
        int j0 = (item >> 5) * JTILE;
        int i0 = (item & (CHUNKS - 1)) * ITILE;
        char* base = stg + (ss & (NBUF - 1)) * STAGE_BYTES;
        int koff = ks * KT;
        #pragma unroll
        for (int u = 0; u < 4; u++) {                 // A = E slab: 128 x 64h
            int uid = u * 256 + tid, row = uid >> 3, c16 = uid & 7;
            int sc = c16 ^ (row & 7);
            cp16(base + row * 128 + sc * 16,
                 g_eh + (size_t)(j0 + row) * DDIM + koff + c16 * 8);
        }
        #pragma unroll
        for (int u = 0; u < 8; u++) {                 // B = Z chunk: 256 x 64h
            int uid = u * 256 + tid, row = uid >> 3, c16 = uid & 7;
            int sc = c16 ^ (row & 7);
            cp16(base + A_BYTES + row * 128 + sc * 16,
                 g_zh + (size_t)(i0 + row) * DDIM + koff + c16 * 8);
        }
        asm volatile("cp.async.commit_group;" ::: "memory");
    };

    // fragment loader for one k16 step (kk) of the stage at smem base Ab/Bb
    auto load_frags = [&](uint32_t Ab, uint32_t Bb, int kk,
                          uint32_t a[4][4], uint32_t b[8][2]) {
        #pragma unroll
        for (int mt = 0; mt < 4; mt++) {
            int row = wm * 64 + mt * 16 + rA;
            int c16 = kk * 2 + cA;
            ldsm_x4(a[mt][0], a[mt][1], a[mt][2], a[mt][3],
                    Ab + row * 128 + ((c16 ^ (row & 7)) << 4));
        }
        #pragma unroll
        for (int u = 0; u < 4; u++) {
            int row = wn * 64 + u * 16 + rB;
            int c16 = kk * 2 + cB;
            ldsm_x4(b[2 * u][0], b[2 * u][1], b[2 * u + 1][0], b[2 * u + 1][1],
                    Bb + row * 128 + ((c16 ^ (row & 7)) << 4));
        }
    };

    issue_stage(0);
    issue_stage(1);

    #pragma unroll 1
    for (int ss = 0; ss < tot; ss++) {
        asm volatile("cp.async.wait_group 1;" ::: "memory");
        __syncthreads();
        const int q = ss >> 3, ks = ss & (KSTAGES - 1);
        const int item = cta + q * GRID;
        const int chunk = item & (CHUNKS - 1);
        const int j0 = (item >> 5) * JTILE;
        if (ks == 0)
            az2[(q & 1) * ITILE + tid] = coefA * g_z2[chunk * ITILE + tid];
        if (ss + 2 < tot) issue_stage(ss + 2);

        const uint32_t Ab = sb32 + (ss & (NBUF - 1)) * STAGE_BYTES;
        const uint32_t Bb = Ab + A_BYTES;

        // software-pipelined fragments: prefetch kk+1 while mma on kk
        uint32_t a[2][4][4], b[2][8][2];
        load_frags(Ab, Bb, 0, a[0], b[0]);
        #pragma unroll
        for (int kk = 0; kk < KT / 16; kk++) {
            int cur = kk & 1;
            if (kk + 1 < KT / 16)
                load_frags(Ab, Bb, kk + 1, a[cur ^ 1], b[cur ^ 1]);
            #pragma unroll
            for (int mt = 0; mt < 4; mt++)
                #pragma unroll
                for (int nt = 0; nt < 8; nt++)
                    mma_f16(acc[mt][nt], a[cur][mt], b[cur][nt]);
        }

        if (ks == KSTAGES - 1) {
            // ---- per-tile epilogue: max + sum over this 128x256 tile ----
            const float* a2 = az2 + (q & 1) * ITILE;
            float mx[8], sv[8];
            #pragma unroll
            for (int r = 0; r < 8; r++) mx[r] = -INFINITY;
            #pragma unroll
            for (int mt = 0; mt < 4; mt++)
                #pragma unroll
                for (int nt = 0; nt < 8; nt++) {
                    int ib = wn * 64 + nt * 8 + 2 * cql;
                    float s0 = fmaf(coefD, acc[mt][nt][0], a2[ib]);
                    float s1 = fmaf(coefD, acc[mt][nt][1], a2[ib + 1]);
                    float s2 = fmaf(coefD, acc[mt][nt][2], a2[ib]);
                    float s3 = fmaf(coefD, acc[mt][nt][3], a2[ib + 1]);
                    acc[mt][nt][0] = s0; acc[mt][nt][1] = s1;
                    acc[mt][nt][2] = s2; acc[mt][nt][3] = s3;
                    mx[mt * 2]     = fmaxf(mx[mt * 2],     fmaxf(s0, s1));
                    mx[mt * 2 + 1] = fmaxf(mx[mt * 2 + 1], fmaxf(s2, s3));
                }
            // bulk exps via integer Schraudolph (fma/alu pipes, no MUFU)
            #pragma unroll
            for (int mt = 0; mt < 4; mt++) {
                const float cm0 = fmaf(-8388608.f, mx[mt * 2],     SEXP2_C);
                const float cm1 = fmaf(-8388608.f, mx[mt * 2 + 1], SEXP2_C);
                float p0 = 0.f, p1 = 0.f;
                #pragma unroll
                for (int nt = 0; nt < 8; nt++) {
                    p0 += sexp2(acc[mt][nt][0], cm0) + sexp2(acc[mt][nt][1], cm0);
                    p1 += sexp2(acc[mt][nt][2], cm1) + sexp2(acc[mt][nt][3], cm1);
                    acc[mt][nt][0] = 0.f; acc[mt][nt][1] = 0.f;
                    acc[mt][nt][2] = 0.f; acc[mt][nt][3] = 0.f;
                }
                sv[mt * 2] = p0; sv[mt * 2 + 1] = p1;
            }
            // merge 4 lanes (cql) sharing each row (exact ex2, few values)
            #pragma unroll
            for (int r = 0; r < 8; r++) {
                #pragma unroll
                for (int off = 1; off < 4; off <<= 1) {
                    float om = __shfl_xor_sync(0xffffffffu, mx[r], off);
                    float os = __shfl_xor_sync(0xffffffffu, sv[r], off);
                    float nm = fmaxf(mx[r], om);
                    sv[r] = sv[r] * fast_exp2(mx[r] - nm) + os * fast_exp2(om - nm);
                    mx[r] = nm;
                }
            }
            __syncthreads();
            if (cql == 0) {
                #pragma unroll
                for (int r = 0; r < 8; r++) {
                    int row = wm * 64 + (r >> 1) * 16 + (r & 1) * 8 + g;
                    smm[wn * JTILE + row] = mx[r];
                    sms[wn * JTILE + row] = sv[r];
                }
            }
            __syncthreads();
            if (tid < JTILE) {
                float gm = -INFINITY;
                #pragma unroll
                for (int w = 0; w < 4; w++) gm = fmaxf(gm, smm[w * JTILE + tid]);
                float gs = 0.f;
                #pragma unroll
                for (int w = 0; w < 4; w++)
                    gs += sms[w * JTILE + tid] * fast_exp2(smm[w * JTILE + tid] - gm);
                g_pm[chunk * MROWS + j0 + tid] = gm;
                g_ps[chunk * MROWS + j0 + tid] = gs;
            }
        }
    }
}

// ---- finalize: merge 32 chunk-partials per column; last block writes out ----
__global__ void finalize_kernel(const float* __restrict__ log_sigma,
                                float* __restrict__ out) {
    __shared__ double red[256];
    int tid = threadIdx.x;
    int j = blockIdx.x * 256 + tid;
    float ls = __ldg(log_sigma);
    float alpha = -0.5f * __expf(-2.f * ls);
    float gm = -INFINITY;
    #pragma unroll
    for (int c = 0; c < CHUNKS; c++) gm = fmaxf(gm, g_pm[c * MROWS + j]);
    float s = 0.f;
    #pragma unroll
    for (int c = 0; c < CHUNKS; c++)
        s += g_ps[c * MROWS + j] * exp2f(g_pm[c * MROWS + j] - gm);
    float lse = alpha * g_e2[j] + LN2 * (gm + log2f(s));
    red[tid] = (double)lse;
    __syncthreads();
    for (int o = 128; o; o >>= 1) { if (tid < o) red[tid] += red[tid + o]; __syncthreads(); }
    if (tid == 0) {
        atomicAdd(&g_acc, red[0]);
        __threadfence();
        unsigned int done = atomicAdd(&g_cnt, 1u);
        if (done == FIN_BLOCKS - 1) {
            double total = atomicAdd(&g_acc, 0.0);
            out[0] = (float)(-total / (double)MROWS)
                   + 0.5f * (float)DDIM * (2.f * ls - 1.f) + logf((float)NROWS);
        }
    }
}

extern "C" void kernel_launch(void* const* d_in, const int* in_sizes, int n_in,
                              void* d_out, int out_size) {
    const float* Z  = (const float*)d_in[0];
    const float* E  = (const float*)d_in[1];
    const float* ls = (const float*)d_in[2];
    float* out = (float*)d_out;

    static int smem_set = 0;
    int smem_bytes = NBUF * STAGE_BYTES + (2 * ITILE + 8 * JTILE) * 4;
    if (!smem_set) {
        cudaFuncSetAttribute(fused_mma_lse,
                             cudaFuncAttributeMaxDynamicSharedMemorySize, smem_bytes);
        smem_set = 1;
    }

    prep_kernel<<<(NROWS + MROWS) / 8, 256>>>(Z, E);
    fused_mma_lse<<<GRID, 256, smem_bytes>>>(ls);
    finalize_kernel<<<FIN_BLOCKS, 256>>>(ls, out);
}

// round 14
// speedup vs baseline: 1.0326x; 1.0326x over previous
#include <cuda_runtime.h>
#include <cuda_fp16.h>
#include <math.h>
#include <stdint.h>

// loss = -mean_j [ alpha*e2_j + logsumexp_i( alpha*z2_i - 2*alpha*<z_i,e_j> ) ]
//        + 0.5*D*(2*ls - 1) + log(N)
// fp16 mma.sync.m16n8k16 (fp32 accum) + ldmatrix + XOR-swizzled smem +
// cp.async pipeline. Persistent 148-CTA grid, static schedule (2048 tiles of
// 128j x 256i x 512k). Register-fragment double buffering hides LDSM latency.
// (Round-8 configuration: empirically optimal across 7 scheduling/ALU variants.)

#define NROWS 8192
#define MROWS 8192
#define DDIM  512

#define JTILE 128
#define ITILE 256
#define KT    64                       // k per stage (128B fp16 rows)
#define KSTAGES (DDIM / KT)            // 8
#define SLABS (MROWS / JTILE)          // 64
#define CHUNKS (NROWS / ITILE)         // 32
#define NITEMS (SLABS * CHUNKS)        // 2048
#define GRID 148

#define A_BYTES (JTILE * 128)          // 16384
#define B_BYTES (ITILE * 128)          // 32768
#define STAGE_BYTES (A_BYTES + B_BYTES)
#define NBUF 4

#define LOG2E 1.4426950408889634f
#define LN2   0.6931471805599453f

#define FIN_BLOCKS (MROWS / 256)       // 32

__device__ __half g_zh[NROWS * DDIM];
__device__ __half g_eh[MROWS * DDIM];
__device__ float g_z2[NROWS];
__device__ float g_e2[MROWS];
__device__ float g_pm[CHUNKS * MROWS];   // per-(chunk,j) max (log2 units)
__device__ float g_ps[CHUNKS * MROWS];   // per-(chunk,j) sum
__device__ double g_acc;
__device__ unsigned int g_cnt;

__device__ __forceinline__ float fast_exp2(float x) {
    float r; asm("ex2.approx.ftz.f32 %0, %1;" : "=f"(r) : "f"(x)); return r;
}
__device__ __forceinline__ void mma_f16(float* d, const uint32_t* a, const uint32_t* b) {
    asm volatile(
        "mma.sync.aligned.m16n8k16.row.col.f32.f16.f16.f32 "
        "{%0,%1,%2,%3}, {%4,%5,%6,%7}, {%8,%9}, {%0,%1,%2,%3};"
        : "+f"(d[0]), "+f"(d[1]), "+f"(d[2]), "+f"(d[3])
        : "r"(a[0]), "r"(a[1]), "r"(a[2]), "r"(a[3]), "r"(b[0]), "r"(b[1]));
}
__device__ __forceinline__ void ldsm_x4(uint32_t& r0, uint32_t& r1,
                                        uint32_t& r2, uint32_t& r3, uint32_t addr) {
    asm volatile("ldmatrix.sync.aligned.m8n8.x4.shared.b16 {%0,%1,%2,%3}, [%4];"
                 : "=r"(r0), "=r"(r1), "=r"(r2), "=r"(r3) : "r"(addr));
}
__device__ __forceinline__ void cp16(void* smem_dst, const void* gmem_src) {
    uint32_t d = (uint32_t)__cvta_generic_to_shared(smem_dst);
    asm volatile("cp.async.cg.shared.global [%0], [%1], 16;"
                 :: "r"(d), "l"(gmem_src) : "memory");
}

// ---- prep: exact fp32 row norms + fp16(rne) copies; zero accumulators ----
__global__ void prep_kernel(const float* __restrict__ Z, const float* __restrict__ E) {
    if (blockIdx.x == 0 && threadIdx.x == 0) { g_acc = 0.0; g_cnt = 0u; }
    int gw = (blockIdx.x * blockDim.x + threadIdx.x) >> 5;
    int lane = threadIdx.x & 31;
    if (gw >= NROWS + MROWS) return;
    const float4* src; uint2* dst;
    if (gw < NROWS) { src = (const float4*)(Z + (size_t)gw * DDIM);
                      dst = (uint2*)(g_zh + (size_t)gw * DDIM); }
    else            { src = (const float4*)(E + (size_t)(gw - NROWS) * DDIM);
                      dst = (uint2*)(g_eh + (size_t)(gw - NROWS) * DDIM); }
    float s = 0.f;
    #pragma unroll
    for (int u = 0; u < DDIM / 4 / 32; u++) {
        float4 v = src[u * 32 + lane];
        s = fmaf(v.x, v.x, s); s = fmaf(v.y, v.y, s);
        s = fmaf(v.z, v.z, s); s = fmaf(v.w, v.w, s);
        __half2 h01 = __floats2half2_rn(v.x, v.y);
        __half2 h23 = __floats2half2_rn(v.z, v.w);
        uint2 w;
        w.x = *reinterpret_cast<uint32_t*>(&h01);
        w.y = *reinterpret_cast<uint32_t*>(&h23);
        dst[u * 32 + lane] = w;
    }
    #pragma unroll
    for (int o = 16; o; o >>= 1) s += __shfl_xor_sync(0xffffffffu, s, o);
    if (lane == 0) { if (gw < NROWS) g_z2[gw] = s; else g_e2[gw - NROWS] = s; }
}

// ---- persistent fused fp16 mma GEMM + per-tile LSE partials ----
__global__ void __launch_bounds__(256, 1) fused_mma_lse(const float* __restrict__ log_sigma) {
    extern __shared__ char smem[];
    char* stg = smem;                                        // NBUF * STAGE_BYTES
    float* az2 = (float*)(smem + NBUF * STAGE_BYTES);        // 2 * ITILE
    float* smm = az2 + 2 * ITILE;                            // 4 * JTILE
    float* sms = smm + 4 * JTILE;                            // 4 * JTILE
    const uint32_t sb32 = (uint32_t)__cvta_generic_to_shared(smem);

    const int tid = threadIdx.x, lane = tid & 31, wid = tid >> 5;
    const int wm = wid & 1, wn = wid >> 1;                   // 2 x 4 warp grid
    const int g = lane >> 2, cql = lane & 3;
    const int cta = blockIdx.x;

    const int nitems = (NITEMS - cta + GRID - 1) / GRID;     // 13 or 14
    const int tot = nitems * KSTAGES;

    // ldmatrix per-lane addressing
    const int rA = ((lane >> 3) & 1) * 8 + (lane & 7);
    const int cA = (lane >> 4) & 1;
    const int rB = ((lane >> 4) & 1) * 8 + (lane & 7);
    const int cB = (lane >> 3) & 1;

    const float ls = __ldg(log_sigma);
    const float alpha = -0.5f * __expf(-2.f * ls);
    const float coefD = LOG2E * (-2.f * alpha);
    const float coefA = LOG2E * alpha;

    float acc[4][8][4];
    #pragma unroll
    for (int mt = 0; mt < 4; mt++)
        #pragma unroll
        for (int nt = 0; nt < 8; nt++)
            #pragma unroll
            for (int q = 0; q < 4; q++) acc[mt][nt][q] = 0.f;

    auto issue_stage = [&](int ss) {
        int q = ss >> 3, ks = ss & (KSTAGES - 1);
        int item = cta + q * GRID;
        int j0 = (item >> 5) * JTILE;
        int i0 = (item & (CHUNKS - 1)) * ITILE;
        char* base = stg + (ss & (NBUF - 1)) * STAGE_BYTES;
        int koff = ks * KT;
        #pragma unroll
        for (int u = 0; u < 4; u++) {                 // A = E slab: 128 x 64h
            int uid = u * 256 + tid, row = uid >> 3, c16 = uid & 7;
            int sc = c16 ^ (row & 7);
            cp16(base + row * 128 + sc * 16,
                 g_eh + (size_t)(j0 + row) * DDIM + koff + c16 * 8);
        }
        #pragma unroll
        for (int u = 0; u < 8; u++) {                 // B = Z chunk: 256 x 64h
            int uid = u * 256 + tid, row = uid >> 3, c16 = uid & 7;
            int sc = c16 ^ (row & 7);
            cp16(base + A_BYTES + row * 128 + sc * 16,
                 g_zh + (size_t)(i0 + row) * DDIM + koff + c16 * 8);
        }
        asm volatile("cp.async.commit_group;" ::: "memory");
    };

    // fragment loader for one k16 step (kk) of the stage at smem base Ab/Bb
    auto load_frags = [&](uint32_t Ab, uint32_t Bb, int kk,
                          uint32_t a[4][4], uint32_t b[8][2]) {
        #pragma unroll
        for (int mt = 0; mt < 4; mt++) {
            int row = wm * 64 + mt * 16 + rA;
            int c16 = kk * 2 + cA;
            ldsm_x4(a[mt][0], a[mt][1], a[mt][2], a[mt][3],
                    Ab + row * 128 + ((c16 ^ (row & 7)) << 4));
        }
        #pragma unroll
        for (int u = 0; u < 4; u++) {
            int row = wn * 64 + u * 16 + rB;
            int c16 = kk * 2 + cB;
            ldsm_x4(b[2 * u][0], b[2 * u][1], b[2 * u + 1][0], b[2 * u + 1][1],
                    Bb + row * 128 + ((c16 ^ (row & 7)) << 4));
        }
    };

    issue_stage(0);
    issue_stage(1);

    #pragma unroll 1
    for (int ss = 0; ss < tot; ss++) {
        asm volatile("cp.async.wait_group 1;" ::: "memory");
        __syncthreads();
        const int q = ss >> 3, ks = ss & (KSTAGES - 1);
        const int item = cta + q * GRID;
        const int chunk = item & (CHUNKS - 1);
        const int j0 = (item >> 5) * JTILE;
        if (ks == 0)
            az2[(q & 1) * ITILE + tid] = coefA * g_z2[chunk * ITILE + tid];
        if (ss + 2 < tot) issue_stage(ss + 2);

        const uint32_t Ab = sb32 + (ss & (NBUF - 1)) * STAGE_BYTES;
        const uint32_t Bb = Ab + A_BYTES;

        // software-pipelined fragments: prefetch kk+1 while mma on kk
        uint32_t a[2][4][4], b[2][8][2];
        load_frags(Ab, Bb, 0, a[0], b[0]);
        #pragma unroll
        for (int kk = 0; kk < KT / 16; kk++) {
            int cur = kk & 1;
            if (kk + 1 < KT / 16)
                load_frags(Ab, Bb, kk + 1, a[cur ^ 1], b[cur ^ 1]);
            #pragma unroll
            for (int mt = 0; mt < 4; mt++)
                #pragma unroll
                for (int nt = 0; nt < 8; nt++)
                    mma_f16(acc[mt][nt], a[cur][mt], b[cur][nt]);
        }

        if (ks == KSTAGES - 1) {
            // ---- per-tile epilogue: max + sum over this 128x256 tile ----
            const float* a2 = az2 + (q & 1) * ITILE;
            float mx[8], sv[8];
            #pragma unroll
            for (int r = 0; r < 8; r++) mx[r] = -INFINITY;
            #pragma unroll
            for (int mt = 0; mt < 4; mt++)
                #pragma unroll
                for (int nt = 0; nt < 8; nt++) {
                    int ib = wn * 64 + nt * 8 + 2 * cql;
                    float s0 = fmaf(coefD, acc[mt][nt][0], a2[ib]);
                    float s1 = fmaf(coefD, acc[mt][nt][1], a2[ib + 1]);
                    float s2 = fmaf(coefD, acc[mt][nt][2], a2[ib]);
                    float s3 = fmaf(coefD, acc[mt][nt][3], a2[ib + 1]);
                    acc[mt][nt][0] = s0; acc[mt][nt][1] = s1;
                    acc[mt][nt][2] = s2; acc[mt][nt][3] = s3;
                    mx[mt * 2]     = fmaxf(mx[mt * 2],     fmaxf(s0, s1));
                    mx[mt * 2 + 1] = fmaxf(mx[mt * 2 + 1], fmaxf(s2, s3));
                }
            #pragma unroll
            for (int mt = 0; mt < 4; mt++) {
                float p0 = 0.f, p1 = 0.f;
                #pragma unroll
                for (int nt = 0; nt < 8; nt++) {
                    p0 += fast_exp2(acc[mt][nt][0] - mx[mt * 2])
                        + fast_exp2(acc[mt][nt][1] - mx[mt * 2]);
                    p1 += fast_exp2(acc[mt][nt][2] - mx[mt * 2 + 1])
                        + fast_exp2(acc[mt][nt][3] - mx[mt * 2 + 1]);
                    acc[mt][nt][0] = 0.f; acc[mt][nt][1] = 0.f;
                    acc[mt][nt][2] = 0.f; acc[mt][nt][3] = 0.f;
                }
                sv[mt * 2] = p0; sv[mt * 2 + 1] = p1;
            }
            // merge 4 lanes (cql) sharing each row
            #pragma unroll
            for (int r = 0; r < 8; r++) {
                #pragma unroll
                for (int off = 1; off < 4; off <<= 1) {
                    float om = __shfl_xor_sync(0xffffffffu, mx[r], off);
                    float os = __shfl_xor_sync(0xffffffffu, sv[r], off);
                    float nm = fmaxf(mx[r], om);
                    sv[r] = sv[r] * fast_exp2(mx[r] - nm) + os * fast_exp2(om - nm);
                    mx[r] = nm;
                }
            }
            __syncthreads();
            if (cql == 0) {
                #pragma unroll
                for (int r = 0; r < 8; r++) {
                    int row = wm * 64 + (r >> 1) * 16 + (r & 1) * 8 + g;
                    smm[wn * JTILE + row] = mx[r];
                    sms[wn * JTILE + row] = sv[r];
                }
            }
            __syncthreads();
            if (tid < JTILE) {
                float gm = -INFINITY;
                #pragma unroll
                for (int w = 0; w < 4; w++) gm = fmaxf(gm, smm[w * JTILE + tid]);
                float gs = 0.f;
                #pragma unroll
                for (int w = 0; w < 4; w++)
                    gs += sms[w * JTILE + tid] * fast_exp2(smm[w * JTILE + tid] - gm);
                g_pm[chunk * MROWS + j0 + tid] = gm;
                g_ps[chunk * MROWS + j0 + tid] = gs;
            }
        }
    }
}

// ---- finalize: merge 32 chunk-partials per column; last block writes out ----
__global__ void finalize_kernel(const float* __restrict__ log_sigma,
                                float* __restrict__ out) {
    __shared__ double red[256];
    int tid = threadIdx.x;
    int j = blockIdx.x * 256 + tid;
    float ls = __ldg(log_sigma);
    float alpha = -0.5f * __expf(-2.f * ls);
    float gm = -INFINITY;
    #pragma unroll
    for (int c = 0; c < CHUNKS; c++) gm = fmaxf(gm, g_pm[c * MROWS + j]);
    float s = 0.f;
    #pragma unroll
    for (int c = 0; c < CHUNKS; c++)
        s += g_ps[c * MROWS + j] * exp2f(g_pm[c * MROWS + j] - gm);
    float lse = alpha * g_e2[j] + LN2 * (gm + log2f(s));
    red[tid] = (double)lse;
    __syncthreads();
    for (int o = 128; o; o >>= 1) { if (tid < o) red[tid] += red[tid + o]; __syncthreads(); }
    if (tid == 0) {
        atomicAdd(&g_acc, red[0]);
        __threadfence();
        unsigned int done = atomicAdd(&g_cnt, 1u);
        if (done == FIN_BLOCKS - 1) {
            double total = atomicAdd(&g_acc, 0.0);
            out[0] = (float)(-total / (double)MROWS)
                   + 0.5f * (float)DDIM * (2.f * ls - 1.f) + logf((float)NROWS);
        }
    }
}

extern "C" void kernel_launch(void* const* d_in, const int* in_sizes, int n_in,
                              void* d_out, int out_size) {
    const float* Z  = (const float*)d_in[0];
    const float* E  = (const float*)d_in[1];
    const float* ls = (const float*)d_in[2];
    float* out = (float*)d_out;

    static int smem_set = 0;
    int smem_bytes = NBUF * STAGE_BYTES + (2 * ITILE + 8 * JTILE) * 4;
    if (!smem_set) {
        cudaFuncSetAttribute(fused_mma_lse,
                             cudaFuncAttributeMaxDynamicSharedMemorySize, smem_bytes);
        smem_set = 1;
    }

    prep_kernel<<<(NROWS + MROWS) / 8, 256>>>(Z, E);
    fused_mma_lse<<<GRID, 256, smem_bytes>>>(ls);
    finalize_kernel<<<FIN_BLOCKS, 256>>>(ls, out);
}

// round 15
// speedup vs baseline: 1.0443x; 1.0113x over previous
#include <cuda_runtime.h>
#include <cuda_fp16.h>
#include <math.h>
#include <stdint.h>

// loss = -mean_j [ alpha*e2_j + logsumexp_i( alpha*z2_i - 2*alpha*<z_i,e_j> ) ]
//        + 0.5*D*(2*ls - 1) + log(N)
// fp16 mma.sync.m16n8k16 (fp32 accum) + ldmatrix + XOR-swizzled smem +
// cp.async double buffer with KT=128 stages (4 lockstep points per item
// instead of 8). Persistent 148-CTA grid, static schedule (2048 tiles of
// 128j x 256i x 512k). Register-fragment double buffering.

#define NROWS 8192
#define MROWS 8192
#define DDIM  512

#define JTILE 128
#define ITILE 256
#define KT    128                      // k per stage (256B fp16 rows)
#define KSTAGES (DDIM / KT)            // 4
#define SLABS (MROWS / JTILE)          // 64
#define CHUNKS (NROWS / ITILE)         // 32
#define NITEMS (SLABS * CHUNKS)        // 2048
#define GRID 148

#define ROWB 256                       // bytes per smem row (KT fp16)
#define A_BYTES (JTILE * ROWB)         // 32768
#define B_BYTES (ITILE * ROWB)         // 65536
#define STAGE_BYTES (A_BYTES + B_BYTES)
#define NBUF 2

#define LOG2E 1.4426950408889634f
#define LN2   0.6931471805599453f

#define FIN_BLOCKS (MROWS / 256)       // 32

__device__ __half g_zh[NROWS * DDIM];
__device__ __half g_eh[MROWS * DDIM];
__device__ float g_z2[NROWS];
__device__ float g_e2[MROWS];
__device__ float g_pm[CHUNKS * MROWS];   // per-(chunk,j) max (log2 units)
__device__ float g_ps[CHUNKS * MROWS];   // per-(chunk,j) sum
__device__ double g_acc;
__device__ unsigned int g_cnt;

__device__ __forceinline__ float fast_exp2(float x) {
    float r; asm("ex2.approx.ftz.f32 %0, %1;" : "=f"(r) : "f"(x)); return r;
}
__device__ __forceinline__ void mma_f16(float* d, const uint32_t* a, const uint32_t* b) {
    asm volatile(
        "mma.sync.aligned.m16n8k16.row.col.f32.f16.f16.f32 "
        "{%0,%1,%2,%3}, {%4,%5,%6,%7}, {%8,%9}, {%0,%1,%2,%3};"
        : "+f"(d[0]), "+f"(d[1]), "+f"(d[2]), "+f"(d[3])
        : "r"(a[0]), "r"(a[1]), "r"(a[2]), "r"(a[3]), "r"(b[0]), "r"(b[1]));
}
__device__ __forceinline__ void ldsm_x4(uint32_t& r0, uint32_t& r1,
                                        uint32_t& r2, uint32_t& r3, uint32_t addr) {
    asm volatile("ldmatrix.sync.aligned.m8n8.x4.shared.b16 {%0,%1,%2,%3}, [%4];"
                 : "=r"(r0), "=r"(r1), "=r"(r2), "=r"(r3) : "r"(addr));
}
__device__ __forceinline__ void cp16(void* smem_dst, const void* gmem_src) {
    uint32_t d = (uint32_t)__cvta_generic_to_shared(smem_dst);
    asm volatile("cp.async.cg.shared.global [%0], [%1], 16;"
                 :: "r"(d), "l"(gmem_src) : "memory");
}

// ---- prep: exact fp32 row norms + fp16(rne) copies; zero accumulators ----
__global__ void prep_kernel(const float* __restrict__ Z, const float* __restrict__ E) {
    if (blockIdx.x == 0 && threadIdx.x == 0) { g_acc = 0.0; g_cnt = 0u; }
    int gw = (blockIdx.x * blockDim.x + threadIdx.x) >> 5;
    int lane = threadIdx.x & 31;
    if (gw >= NROWS + MROWS) return;
    const float4* src; uint2* dst;
    if (gw < NROWS) { src = (const float4*)(Z + (size_t)gw * DDIM);
                      dst = (uint2*)(g_zh + (size_t)gw * DDIM); }
    else            { src = (const float4*)(E + (size_t)(gw - NROWS) * DDIM);
                      dst = (uint2*)(g_eh + (size_t)(gw - NROWS) * DDIM); }
    float s = 0.f;
    #pragma unroll
    for (int u = 0; u < DDIM / 4 / 32; u++) {
        float4 v = src[u * 32 + lane];
        s = fmaf(v.x, v.x, s); s = fmaf(v.y, v.y, s);
        s = fmaf(v.z, v.z, s); s = fmaf(v.w, v.w, s);
        __half2 h01 = __floats2half2_rn(v.x, v.y);
        __half2 h23 = __floats2half2_rn(v.z, v.w);
        uint2 w;
        w.x = *reinterpret_cast<uint32_t*>(&h01);
        w.y = *reinterpret_cast<uint32_t*>(&h23);
        dst[u * 32 + lane] = w;
    }
    #pragma unroll
    for (int o = 16; o; o >>= 1) s += __shfl_xor_sync(0xffffffffu, s, o);
    if (lane == 0) { if (gw < NROWS) g_z2[gw] = s; else g_e2[gw - NROWS] = s; }
}

// ---- persistent fused fp16 mma GEMM + per-tile LSE partials ----
__global__ void __launch_bounds__(256, 1) fused_mma_lse(const float* __restrict__ log_sigma) {
    extern __shared__ char smem[];
    char* stg = smem;                                        // NBUF * STAGE_BYTES
    float* az2 = (float*)(smem + NBUF * STAGE_BYTES);        // 2 * ITILE
    float* smm = az2 + 2 * ITILE;                            // 4 * JTILE
    float* sms = smm + 4 * JTILE;                            // 4 * JTILE
    const uint32_t sb32 = (uint32_t)__cvta_generic_to_shared(smem);

    const int tid = threadIdx.x, lane = tid & 31, wid = tid >> 5;
    const int wm = wid & 1, wn = wid >> 1;                   // 2 x 4 warp grid
    const int g = lane >> 2, cql = lane & 3;
    const int cta = blockIdx.x;

    const int nitems = (NITEMS - cta + GRID - 1) / GRID;     // 13 or 14
    const int tot = nitems * KSTAGES;

    // ldmatrix per-lane addressing
    const int rA = ((lane >> 3) & 1) * 8 + (lane & 7);
    const int cA = (lane >> 4) & 1;
    const int rB = ((lane >> 4) & 1) * 8 + (lane & 7);
    const int cB = (lane >> 3) & 1;

    const float ls = __ldg(log_sigma);
    const float alpha = -0.5f * __expf(-2.f * ls);
    const float coefD = LOG2E * (-2.f * alpha);
    const float coefA = LOG2E * alpha;

    float acc[4][8][4];
    #pragma unroll
    for (int mt = 0; mt < 4; mt++)
        #pragma unroll
        for (int nt = 0; nt < 8; nt++)
            #pragma unroll
            for (int q = 0; q < 4; q++) acc[mt][nt][q] = 0.f;

    auto issue_stage = [&](int ss) {
        int q = ss >> 2, ks = ss & (KSTAGES - 1);
        int item = cta + q * GRID;
        int j0 = (item >> 5) * JTILE;
        int i0 = (item & (CHUNKS - 1)) * ITILE;
        char* base = stg + (ss & (NBUF - 1)) * STAGE_BYTES;
        int koff = ks * KT;
        #pragma unroll
        for (int u = 0; u < 8; u++) {                 // A = E slab: 128 x 128h
            int uid = u * 256 + tid, row = uid >> 4, c16 = uid & 15;
            int sc = c16 ^ (row & 7);
            cp16(base + row * ROWB + sc * 16,
                 g_eh + (size_t)(j0 + row) * DDIM + koff + c16 * 8);
        }
        #pragma unroll
        for (int u = 0; u < 16; u++) {                // B = Z chunk: 256 x 128h
            int uid = u * 256 + tid, row = uid >> 4, c16 = uid & 15;
            int sc = c16 ^ (row & 7);
            cp16(base + A_BYTES + row * ROWB + sc * 16,
                 g_zh + (size_t)(i0 + row) * DDIM + koff + c16 * 8);
        }
        asm volatile("cp.async.commit_group;" ::: "memory");
    };

    // fragment loader for one k16 step (kk in 0..7) at smem base Ab/Bb
    auto load_frags = [&](uint32_t Ab, uint32_t Bb, int kk,
                          uint32_t a[4][4], uint32_t b[8][2]) {
        #pragma unroll
        for (int mt = 0; mt < 4; mt++) {
            int row = wm * 64 + mt * 16 + rA;
            int c16 = kk * 2 + cA;
            ldsm_x4(a[mt][0], a[mt][1], a[mt][2], a[mt][3],
                    Ab + row * ROWB + ((c16 ^ (row & 7)) << 4));
        }
        #pragma unroll
        for (int u = 0; u < 4; u++) {
            int row = wn * 64 + u * 16 + rB;
            int c16 = kk * 2 + cB;
            ldsm_x4(b[2 * u][0], b[2 * u][1], b[2 * u + 1][0], b[2 * u + 1][1],
                    Bb + row * ROWB + ((c16 ^ (row & 7)) << 4));
        }
    };

    issue_stage(0);

    #pragma unroll 1
    for (int ss = 0; ss < tot; ss++) {
        asm volatile("cp.async.wait_group 0;" ::: "memory");
        __syncthreads();
        const int q = ss >> 2, ks = ss & (KSTAGES - 1);
        const int item = cta + q * GRID;
        const int chunk = item & (CHUNKS - 1);
        const int j0 = (item >> 5) * JTILE;
        if (ss + 1 < tot) issue_stage(ss + 1);
        if (ks == 0)
            az2[(q & 1) * ITILE + tid] = coefA * g_z2[chunk * ITILE + tid];

        const uint32_t Ab = sb32 + (ss & (NBUF - 1)) * STAGE_BYTES;
        const uint32_t Bb = Ab + A_BYTES;

        // software-pipelined fragments: prefetch kk+1 while mma on kk
        uint32_t a[2][4][4], b[2][8][2];
        load_frags(Ab, Bb, 0, a[0], b[0]);
        #pragma unroll
        for (int kk = 0; kk < KT / 16; kk++) {
            int cur = kk & 1;
            if (kk + 1 < KT / 16)
                load_frags(Ab, Bb, kk + 1, a[cur ^ 1], b[cur ^ 1]);
            #pragma unroll
            for (int mt = 0; mt < 4; mt++)
                #pragma unroll
                for (int nt = 0; nt < 8; nt++)
                    mma_f16(acc[mt][nt], a[cur][mt], b[cur][nt]);
        }

        if (ks == KSTAGES - 1) {
            // ---- per-tile epilogue: max + sum over this 128x256 tile ----
            const float* a2 = az2 + (q & 1) * ITILE;
            float mx[8], sv[8];
            #pragma unroll
            for (int r = 0; r < 8; r++) mx[r] = -INFINITY;
            #pragma unroll
            for (int mt = 0; mt < 4; mt++)
                #pragma unroll
                for (int nt = 0; nt < 8; nt++) {
                    int ib = wn * 64 + nt * 8 + 2 * cql;
                    float s0 = fmaf(coefD, acc[mt][nt][0], a2[ib]);
                    float s1 = fmaf(coefD, acc[mt][nt][1], a2[ib + 1]);
                    float s2 = fmaf(coefD, acc[mt][nt][2], a2[ib]);
                    float s3 = fmaf(coefD, acc[mt][nt][3], a2[ib + 1]);
                    acc[mt][nt][0] = s0; acc[mt][nt][1] = s1;
                    acc[mt][nt][2] = s2; acc[mt][nt][3] = s3;
                    mx[mt * 2]     = fmaxf(mx[mt * 2],     fmaxf(s0, s1));
                    mx[mt * 2 + 1] = fmaxf(mx[mt * 2 + 1], fmaxf(s2, s3));
                }
            #pragma unroll
            for (int mt = 0; mt < 4; mt++) {
                float p0 = 0.f, p1 = 0.f;
                #pragma unroll
                for (int nt = 0; nt < 8; nt++) {
                    p0 += fast_exp2(acc[mt][nt][0] - mx[mt * 2])
                        + fast_exp2(acc[mt][nt][1] - mx[mt * 2]);
                    p1 += fast_exp2(acc[mt][nt][2] - mx[mt * 2 + 1])
                        + fast_exp2(acc[mt][nt][3] - mx[mt * 2 + 1]);
                    acc[mt][nt][0] = 0.f; acc[mt][nt][1] = 0.f;
                    acc[mt][nt][2] = 0.f; acc[mt][nt][3] = 0.f;
                }
                sv[mt * 2] = p0; sv[mt * 2 + 1] = p1;
            }
            // merge 4 lanes (cql) sharing each row
            #pragma unroll
            for (int r = 0; r < 8; r++) {
                #pragma unroll
                for (int off = 1; off < 4; off <<= 1) {
                    float om = __shfl_xor_sync(0xffffffffu, mx[r], off);
                    float os = __shfl_xor_sync(0xffffffffu, sv[r], off);
                    float nm = fmaxf(mx[r], om);
                    sv[r] = sv[r] * fast_exp2(mx[r] - nm) + os * fast_exp2(om - nm);
                    mx[r] = nm;
                }
            }
            __syncthreads();
            if (cql == 0) {
                #pragma unroll
                for (int r = 0; r < 8; r++) {
                    int row = wm * 64 + (r >> 1) * 16 + (r & 1) * 8 + g;
                    smm[wn * JTILE + row] = mx[r];
                    sms[wn * JTILE + row] = sv[r];
                }
            }
            __syncthreads();
            if (tid < JTILE) {
                float gm = -INFINITY;
                #pragma unroll
                for (int w = 0; w < 4; w++) gm = fmaxf(gm, smm[w * JTILE + tid]);
                float gs = 0.f;
                #pragma unroll
                for (int w = 0; w < 4; w++)
                    gs += sms[w * JTILE + tid] * fast_exp2(smm[w * JTILE + tid] - gm);
                g_pm[chunk * MROWS + j0 + tid] = gm;
                g_ps[chunk * MROWS + j0 + tid] = gs;
            }
        }
    }
}

// ---- finalize: merge 32 chunk-partials per column; last block writes out ----
__global__ void finalize_kernel(const float* __restrict__ log_sigma,
                                float* __restrict__ out) {
    __shared__ double red[256];
    int tid = threadIdx.x;
    int j = blockIdx.x * 256 + tid;
    float ls = __ldg(log_sigma);
    float alpha = -0.5f * __expf(-2.f * ls);
    float gm = -INFINITY;
    #pragma unroll
    for (int c = 0; c < CHUNKS; c++) gm = fmaxf(gm, g_pm[c * MROWS + j]);
    float s = 0.f;
    #pragma unroll
    for (int c = 0; c < CHUNKS; c++)
        s += g_ps[c * MROWS + j] * exp2f(g_pm[c * MROWS + j] - gm);
    float lse = alpha * g_e2[j] + LN2 * (gm + log2f(s));
    red[tid] = (double)lse;
    __syncthreads();
    for (int o = 128; o; o >>= 1) { if (tid < o) red[tid] += red[tid + o]; __syncthreads(); }
    if (tid == 0) {
        atomicAdd(&g_acc, red[0]);
        __threadfence();
        unsigned int done = atomicAdd(&g_cnt, 1u);
        if (done == FIN_BLOCKS - 1) {
            double total = atomicAdd(&g_acc, 0.0);
            out[0] = (float)(-total / (double)MROWS)
                   + 0.5f * (float)DDIM * (2.f * ls - 1.f) + logf((float)NROWS);
        }
    }
}

extern "C" void kernel_launch(void* const* d_in, const int* in_sizes, int n_in,
                              void* d_out, int out_size) {
    const float* Z  = (const float*)d_in[0];
    const float* E  = (const float*)d_in[1];
    const float* ls = (const float*)d_in[2];
    float* out = (float*)d_out;

    static int smem_set = 0;
    int smem_bytes = NBUF * STAGE_BYTES + (2 * ITILE + 8 * JTILE) * 4;
    if (!smem_set) {
        cudaFuncSetAttribute(fused_mma_lse,
                             cudaFuncAttributeMaxDynamicSharedMemorySize, smem_bytes);
        smem_set = 1;
    }

    prep_kernel<<<(NROWS + MROWS) / 8, 256>>>(Z, E);
    fused_mma_lse<<<GRID, 256, smem_bytes>>>(ls);
    finalize_kernel<<<FIN_BLOCKS, 256>>>(ls, out);
}